// round 15
// baseline (speedup 1.0000x reference)
#include <cuda_runtime.h>
#include <cuda_fp16.h>
#include <cstdint>
#include <string.h>
#include <math.h>

// Problem dims (fixed by the dataset)
#define Bc 256
#define Nc 4096
#define Mc 16384
#define STEPS 50

// ---------------------------------------------------------------------------
// Device-global scratch
// ---------------------------------------------------------------------------
__device__ __half g_Wh[(size_t)Mc * Nc];    // W fp16 [m][n] (written step 0)
__device__ __half g_sh[(size_t)Bc * Nc];    // state fp16 [b][n]
__device__ __half g_fh[(size_t)Bc * Mc];    // e = exp(beta*h) fp16 [b][m]
__device__ float  g_fsumP[2][Bc];           // parity row sums
__device__ float  g_vpart[4][(size_t)Bc * Nc];
__device__ float  g_norm[STEPS];
__device__ unsigned g_cntP[2][4];           // parity per-slice g1 completion
__device__ unsigned g_tickP[2];             // parity g2 ticket counters

__device__ unsigned g_cnt_bar;
__device__ volatile unsigned g_gen_bar;

// ---------------------------------------------------------------------------
// PTX helpers (sm_80-era, legal on plain sm_103)
// ---------------------------------------------------------------------------
__device__ __forceinline__ uint32_t s2u(const void* p) {
    return (uint32_t)__cvta_generic_to_shared(p);
}
__device__ __forceinline__ uint32_t h2u(__half2 h) {
    uint32_t u;
    memcpy(&u, &h, 4);
    return u;
}
__device__ __forceinline__ void cpa16(uint32_t dst, const void* src) {
    asm volatile("cp.async.cg.shared.global [%0], [%1], 16;" :: "r"(dst), "l"(src));
}
#define CP_COMMIT() asm volatile("cp.async.commit_group;" ::: "memory")
#define CP_WAIT(n)  asm volatile("cp.async.wait_group %0;" :: "n"(n) : "memory")

__device__ __forceinline__ void ldm4(uint32_t* r, uint32_t addr) {
    asm volatile("ldmatrix.sync.aligned.m8n8.x4.shared.b16 {%0,%1,%2,%3}, [%4];"
                 : "=r"(r[0]), "=r"(r[1]), "=r"(r[2]), "=r"(r[3]) : "r"(addr));
}
__device__ __forceinline__ void ldm4t(uint32_t* r, uint32_t addr) {
    asm volatile("ldmatrix.sync.aligned.m8n8.x4.trans.shared.b16 {%0,%1,%2,%3}, [%4];"
                 : "=r"(r[0]), "=r"(r[1]), "=r"(r[2]), "=r"(r[3]) : "r"(addr));
}
__device__ __forceinline__ void mma16816(float* d, const uint32_t* a,
                                         uint32_t b0, uint32_t b1) {
    asm volatile(
        "mma.sync.aligned.m16n8k16.row.col.f32.f16.f16.f32 "
        "{%0,%1,%2,%3}, {%4,%5,%6,%7}, {%8,%9}, {%0,%1,%2,%3};"
        : "+f"(d[0]), "+f"(d[1]), "+f"(d[2]), "+f"(d[3])
        : "r"(a[0]), "r"(a[1]), "r"(a[2]), "r"(a[3]), "r"(b0), "r"(b1));
}

// ---------------------------------------------------------------------------
// Software global barrier (grid == #SMs, 1 CTA/SM -> co-resident)
// ---------------------------------------------------------------------------
__device__ __forceinline__ void gbar(int G) {
    __syncthreads();
    if (threadIdx.x == 0) {
        __threadfence();
        unsigned my = g_gen_bar;
        unsigned old = atomicAdd(&g_cnt_bar, 1u);
        if (old == (unsigned)G - 1u) {
            g_cnt_bar = 0u;
            __threadfence();
            g_gen_bar = my + 1u;
        } else {
            while (g_gen_bar == my) __nanosleep(64);
        }
        __threadfence();
    }
    __syncthreads();
}

// ---------------------------------------------------------------------------
// Tiny init: state <- input (+fp16), zero all step state (W handled in-step)
// ---------------------------------------------------------------------------
__global__ void __launch_bounds__(256) k_init0(const float* __restrict__ inp,
                                               float* __restrict__ state) {
    size_t i = (size_t)blockIdx.x * 1024 + threadIdx.x * 4;
    float4 s = *(const float4*)(inp + i);
    *(float4*)(state + i) = s;
    *(__half2*)(g_sh + i)     = __floats2half2_rn(s.x, s.y);
    *(__half2*)(g_sh + i + 2) = __floats2half2_rn(s.z, s.w);

    int gid = blockIdx.x * 256 + threadIdx.x;
    if (gid < STEPS) g_norm[gid] = 0.0f;
    if (gid < Bc) { g_fsumP[0][gid] = 0.0f; g_fsumP[1][gid] = 0.0f; }
    if (gid < 4)  { g_cntP[0][gid] = 0u;    g_cntP[1][gid] = 0u; }
    if (gid == 4) { g_tickP[0] = 0u;        g_tickP[1] = 0u; }
}

// ---------------------------------------------------------------------------
// Shared sizes (R13-proven)
// ---------------------------------------------------------------------------
#define KCH    64
#define ROWB   144                   // K-major row stride (128B + 16B pad)
#define A1_T   (256 * ROWB)          // 36864 B (A tile, 256 rows)
#define STG1   (A1_T + 128 * ROWB)   // 55296 B (GEMM1 stage)
#define STG2   (A1_T + 64 * 256)     // 53248 B (GEMM2 stage)
#define SMEM_T (2 * STG1)            // 110592 B

// ---------------------------------------------------------------------------
// GEMM1 tile: C[256(b) x 128(m)] = state[b][k] * W[m][k], K=4096, 128 tiles.
// 16 warps 4(b) x 4(m), warp tile 64x32. 2-stage cp.async, 1 sync/chunk.
// CONV=1 (step 0 only): B loaded as fp32 from W, converted in regs,
// STS'd to the same swizzled layout AND STG'd to g_Wh for all later readers.
// Epilogue: e = __expf(beta*acc) -> g_fh + row sums; then slice-signal.
// ---------------------------------------------------------------------------
__device__ __forceinline__ void load_g1A(uint32_t sbase, int tid, int ch) {
#pragma unroll
    for (int t2 = 0; t2 < 4; t2++) {           // A: 256 rows x 8 segs
        int idx = tid + t2 * 512;
        int r = idx >> 3, q = idx & 7;
        cpa16(sbase + (uint32_t)(r * ROWB + q * 16),
              g_sh + (size_t)r * Nc + ch * KCH + q * 8);
    }
}
__device__ __forceinline__ void load_g1B(uint32_t sbase, int tid,
                                         const __half* Bp, int ch) {
#pragma unroll
    for (int t2 = 0; t2 < 2; t2++) {           // B: 128 rows x 8 segs
        int idx = tid + t2 * 512;
        int r = idx >> 3, q = idx & 7;
        cpa16(sbase + A1_T + (uint32_t)(r * ROWB + q * 16),
              Bp + (size_t)r * Nc + ch * KCH + q * 8);
    }
}
// CONV: each thread owns row r = tid>>2, col-group g = tid&3 (16 fp32 cols)
__device__ __forceinline__ void ldg_wf32(float4* br, const float* __restrict__ W,
                                         int c0, int tid, int ch) {
    const int r = tid >> 2, g = tid & 3;
    const float* src = W + (size_t)(c0 + r) * Nc + ch * KCH + g * 16;
#pragma unroll
    for (int j = 0; j < 4; j++) br[j] = *(const float4*)(src + j * 4);
}
__device__ __forceinline__ void sts_conv(uint32_t sbase, const float4* br,
                                         int c0, int tid, int ch) {
    const int r = tid >> 2, g = tid & 3;
    uint32_t h[8];
#pragma unroll
    for (int j = 0; j < 4; j++) {
        h[j * 2]     = h2u(__floats2half2_rn(br[j].x, br[j].y));
        h[j * 2 + 1] = h2u(__floats2half2_rn(br[j].z, br[j].w));
    }
    uint32_t so = sbase + A1_T + (uint32_t)(r * ROWB + g * 32);
    asm volatile("st.shared.v4.b32 [%0], {%1,%2,%3,%4};"
                 :: "r"(so), "r"(h[0]), "r"(h[1]), "r"(h[2]), "r"(h[3]));
    asm volatile("st.shared.v4.b32 [%0], {%1,%2,%3,%4};"
                 :: "r"(so + 16), "r"(h[4]), "r"(h[5]), "r"(h[6]), "r"(h[7]));
    uint4* dst = (uint4*)(g_Wh + (size_t)(c0 + r) * Nc + ch * KCH + g * 16);
    *dst = make_uint4(h[0], h[1], h[2], h[3]);
    *(dst + 1) = make_uint4(h[4], h[5], h[6], h[7]);
}

template <int CONV>
__device__ void g1_tile(char* smem, int t, float beta,
                        float* fsumA, unsigned* cntA,
                        const float* __restrict__ W) {
    const int tid = threadIdx.x;
    const int wid = tid >> 5;
    const int lid = tid & 31;
    const int rw  = wid & 3;
    const int cw  = wid >> 2;
    const uint32_t sb = s2u(smem);

    const int c0 = t * 128;
    const __half* Bp = g_Wh + (size_t)c0 * Nc;

    float acc[4][4][4];
#pragma unroll
    for (int i = 0; i < 4; i++)
#pragma unroll
        for (int j = 0; j < 4; j++)
#pragma unroll
            for (int v = 0; v < 4; v++) acc[i][j][v] = 0.0f;

    const int lrow = ((lid >> 3) & 1) * 8 + (lid & 7);
    const int lkb  = (lid >> 4) * 16;

    float4 br[4];
    if (CONV) {
        ldg_wf32(br, W, c0, tid, 0);
        sts_conv(sb, br, c0, tid, 0);          // B(0) -> stage 0
        ldg_wf32(br, W, c0, tid, 1);           // B(1) in regs
    }
    load_g1A(sb, tid, 0);
    if (!CONV) load_g1B(sb, tid, Bp, 0);
    CP_COMMIT();

    for (int ch = 0; ch < 64; ++ch) {
        const uint32_t cur = sb + (uint32_t)(ch & 1) * STG1;
        CP_WAIT(0);
        __syncthreads();
        if (ch + 1 < 64) {
            const uint32_t nxt = sb + (uint32_t)((ch + 1) & 1) * STG1;
            load_g1A(nxt, tid, ch + 1);
            if (CONV) {
                sts_conv(nxt, br, c0, tid, ch + 1);
                if (ch + 2 < 64) ldg_wf32(br, W, c0, tid, ch + 2);
            } else {
                load_g1B(nxt, tid, Bp, ch + 1);
            }
            CP_COMMIT();
        }

#pragma unroll
        for (int ks = 0; ks < 4; ++ks) {
            uint32_t aF[4][4];
            uint32_t bF[2][4];
#pragma unroll
            for (int sub = 0; sub < 4; ++sub) {
                uint32_t ra = (uint32_t)((rw * 64 + sub * 16 + lrow) * ROWB
                                         + ks * 32 + lkb);
                ldm4(aF[sub], cur + ra);
            }
#pragma unroll
            for (int cg = 0; cg < 2; ++cg) {
                uint32_t rb = (uint32_t)((cw * 32 + cg * 16 + lrow) * ROWB
                                         + ks * 32 + lkb);
                ldm4(bF[cg], cur + A1_T + rb);
            }
#pragma unroll
            for (int sub = 0; sub < 4; ++sub)
#pragma unroll
                for (int cg = 0; cg < 2; ++cg)
#pragma unroll
                    for (int hf = 0; hf < 2; ++hf)
                        mma16816(acc[sub][cg * 2 + hf], aF[sub],
                                 bF[cg][hf], bF[cg][hf + 2]);
        }
    }
    __syncthreads();   // stages dead; smem reusable

    // Epilogue: e = __expf(beta*h) -> fp16 g_fh; row sums -> fsumA
    const int gr = lid >> 2;
    const int gc = (lid & 3) * 2;
    float* rsum = (float*)smem;
    if (tid < 256) rsum[tid] = 0.0f;
    __syncthreads();

#pragma unroll
    for (int sub = 0; sub < 4; ++sub) {
        const int rbase = rw * 64 + sub * 16 + gr;
        float s0 = 0.0f, s1 = 0.0f;
#pragma unroll
        for (int nt = 0; nt < 4; ++nt) {
            float e0 = __expf(beta * acc[sub][nt][0]);
            float e1 = __expf(beta * acc[sub][nt][1]);
            float e2 = __expf(beta * acc[sub][nt][2]);
            float e3 = __expf(beta * acc[sub][nt][3]);
            const int col = c0 + cw * 32 + nt * 8 + gc;
            *(__half2*)(g_fh + (size_t)rbase * Mc + col) =
                __floats2half2_rn(e0, e1);
            *(__half2*)(g_fh + (size_t)(rbase + 8) * Mc + col) =
                __floats2half2_rn(e2, e3);
            s0 += e0 + e1;
            s1 += e2 + e3;
        }
        s0 += __shfl_xor_sync(0xFFFFFFFF, s0, 1);
        s0 += __shfl_xor_sync(0xFFFFFFFF, s0, 2);
        s1 += __shfl_xor_sync(0xFFFFFFFF, s1, 1);
        s1 += __shfl_xor_sync(0xFFFFFFFF, s1, 2);
        if ((lid & 3) == 0) {
            atomicAdd(&rsum[rbase], s0);
            atomicAdd(&rsum[rbase + 8], s1);
        }
    }
    __syncthreads();
    if (tid < 256) atomicAdd(&fsumA[tid], rsum[tid]);
    // release: g_fh stores (+ g_Wh stores in CONV) + fsum, then slice signal
    __threadfence();
    __syncthreads();
    if (tid == 0) atomicAdd(&cntA[t >> 5], 1u);
}

// ---------------------------------------------------------------------------
// GEMM2 tile: u[256(b) x 128(n)] = e[b][k] * W[k][n], z-split 4 (K=4096 each),
// 128 tiles, z = t>>5. ldmatrix.trans for W. (R13-proven)
// ---------------------------------------------------------------------------
__device__ __forceinline__ void load_g2(uint32_t sbase, int tid,
                                        const __half* Ap, const __half* Bp, int ch) {
#pragma unroll
    for (int t2 = 0; t2 < 4; t2++) {           // A: 256 rows x 8 segs (K-major)
        int idx = tid + t2 * 512;
        int r = idx >> 3, q = idx & 7;
        cpa16(sbase + (uint32_t)(r * ROWB + q * 16),
              Ap + (size_t)r * Mc + ch * KCH + q * 8);
    }
#pragma unroll
    for (int t2 = 0; t2 < 2; t2++) {           // B: 64 k-rows x 16 segs, XOR sw
        int idx = tid + t2 * 512;
        int r = idx >> 4, q = idx & 15;
        cpa16(sbase + A1_T + (uint32_t)(r * 256 + ((q ^ (r & 7)) * 16)),
              Bp + (size_t)(ch * KCH + r) * Nc + q * 8);
    }
}

__device__ void g2_tile(char* smem, int t) {
    const int tid = threadIdx.x;
    const int wid = tid >> 5;
    const int lid = tid & 31;
    const int rw  = wid & 3;
    const int cw  = wid >> 2;
    const uint32_t sb = s2u(smem);

    const int z  = t >> 5;
    const int c0 = (t & 31) * 128;
    const size_t koff = (size_t)z * 4096;

    const __half* Ap = g_fh + koff;
    const __half* Bp = g_Wh + koff * Nc + c0;
    float* out = &g_vpart[z][0];

    float acc[4][4][4];
#pragma unroll
    for (int i = 0; i < 4; i++)
#pragma unroll
        for (int j = 0; j < 4; j++)
#pragma unroll
            for (int v = 0; v < 4; v++) acc[i][j][v] = 0.0f;

    const int lrow = ((lid >> 3) & 1) * 8 + (lid & 7);
    const int lkb  = (lid >> 4) * 16;
    const int kr   = ((lid >> 4) & 1) * 8 + (lid & 7);
    const int nso  = (lid >> 3) & 1;

    load_g2(sb, tid, Ap, Bp, 0);
    CP_COMMIT();

    for (int ch = 0; ch < 64; ++ch) {
        const uint32_t cur = sb + (uint32_t)(ch & 1) * STG2;
        CP_WAIT(0);
        __syncthreads();
        if (ch + 1 < 64) {
            load_g2(sb + (uint32_t)((ch + 1) & 1) * STG2, tid, Ap, Bp, ch + 1);
            CP_COMMIT();
        }

#pragma unroll
        for (int ks = 0; ks < 4; ++ks) {
            uint32_t aF[4][4];
            uint32_t bF[2][4];
#pragma unroll
            for (int sub = 0; sub < 4; ++sub) {
                uint32_t ra = (uint32_t)((rw * 64 + sub * 16 + lrow) * ROWB
                                         + ks * 32 + lkb);
                ldm4(aF[sub], cur + ra);
            }
#pragma unroll
            for (int cg = 0; cg < 2; ++cg) {
                const int nseg = cw * 4 + cg * 2 + nso;
                uint32_t rb = (uint32_t)((ks * 16 + kr) * 256
                                         + ((nseg ^ (lid & 7)) * 16));
                ldm4t(bF[cg], cur + A1_T + rb);
            }
#pragma unroll
            for (int sub = 0; sub < 4; ++sub)
#pragma unroll
                for (int cg = 0; cg < 2; ++cg)
#pragma unroll
                    for (int hf = 0; hf < 2; ++hf)
                        mma16816(acc[sub][cg * 2 + hf], aF[sub],
                                 bF[cg][hf], bF[cg][hf + 2]);
        }
    }
    __syncthreads();

    const int gr = lid >> 2;
    const int gc = (lid & 3) * 2;
#pragma unroll
    for (int sub = 0; sub < 4; ++sub) {
        const int rbase = rw * 64 + sub * 16 + gr;
#pragma unroll
        for (int nt = 0; nt < 4; ++nt) {
            const int col = c0 + cw * 32 + nt * 8 + gc;
            *(float2*)(out + (size_t)rbase * Nc + col) =
                make_float2(acc[sub][nt][0], acc[sub][nt][1]);
            *(float2*)(out + (size_t)(rbase + 8) * Nc + col) =
                make_float2(acc[sub][nt][2], acc[sub][nt][3]);
        }
    }
    __syncthreads();
}

// ---------------------------------------------------------------------------
// Persistent kernel: all steps; g1->g2 overlapped via per-slice dataflow;
// step-0 GEMM1 also performs the W fp32->fp16 conversion.
// ---------------------------------------------------------------------------
__global__ void __launch_bounds__(512, 1) k_steps(float* __restrict__ state,
                                                  const float* __restrict__ W,
                                                  const float* __restrict__ beta_p,
                                                  const float* __restrict__ tau_p,
                                                  int G) {
    extern __shared__ char smem[];
    float* red = (float*)smem;
    const int tid = threadIdx.x;
    const float beta = *beta_p;
    const float invtau = 1.0f / (*tau_p);

    for (int step = 0; step < STEPS; ++step) {
        const int p = step & 1;
        float*    fsumA = g_fsumP[p];
        unsigned* cntA  = g_cntP[p];

        // GEMM1 + fused exp/rowsum (128 tiles); slice-signals g2
        if (step == 0) {
            for (int t = blockIdx.x; t < 128; t += G)
                g1_tile<1>(smem, t, beta, fsumA, cntA, W);
        } else {
            for (int t = blockIdx.x; t < 128; t += G)
                g1_tile<0>(smem, t, beta, fsumA, cntA, W);
        }

        // GEMM2 (128 tiles, ticket-dispatched, waits only on its slice)
        for (;;) {
            int* ts = (int*)smem;
            if (tid == 0) ts[0] = (int)atomicAdd(&g_tickP[p], 1u);
            __syncthreads();
            const int t = ts[0];
            __syncthreads();
            if (t >= 128) break;
            if (tid == 0) {
                while (*((volatile unsigned*)&g_cntP[p][t >> 5]) < 32u)
                    __nanosleep(32);
            }
            __syncthreads();
            g2_tile(smem, t);
        }
        gbar(G);

        // Update + norm (v = (sum of 4 partials) / rowsum); zero next-parity
        if (blockIdx.x == 0) {
            if (tid < Bc) g_fsumP[p ^ 1][tid] = 0.0f;
            if (tid < 4)  g_cntP[p ^ 1][tid] = 0u;
            if (tid == 4) g_tickP[p ^ 1] = 0u;
        }
        float sumsq = 0.0f;
        for (int i = blockIdx.x * 512 + tid; i < Bc * Nc; i += G * 512) {
            int b = i >> 12;                        // Nc = 4096
            float v = (g_vpart[0][i] + g_vpart[1][i] +
                       g_vpart[2][i] + g_vpart[3][i]) / fsumA[b];
            float so = state[i];
            float nv = so + invtau * (v - so);
            float d = nv - so;
            sumsq += d * d;
            state[i] = nv;
            g_sh[i] = __float2half(nv);
        }
        red[tid] = sumsq;
        __syncthreads();
        for (int s = 256; s > 0; s >>= 1) {
            if (tid < s) red[tid] += red[tid + s];
            __syncthreads();
        }
        if (tid == 0) atomicAdd(&g_norm[step], red[0]);
        gbar(G);

        float nrm = *(volatile float*)&g_norm[step];
        if (sqrtf(nrm) <= 1e-3f) break;
        __syncthreads();
    }
}

// ---------------------------------------------------------------------------
// kernel_launch
// ---------------------------------------------------------------------------
extern "C" void kernel_launch(void* const* d_in, const int* in_sizes, int n_in,
                              void* d_out, int out_size) {
    const float* inp  = (const float*)d_in[0];
    const float* W    = (const float*)d_in[1];
    const float* beta = (const float*)d_in[2];
    const float* tau  = (const float*)d_in[3];
    float* state = (float*)d_out;

    int dev = 0;
    cudaGetDevice(&dev);
    cudaDeviceProp props;
    cudaGetDeviceProperties(&props, dev);
    const int G = props.multiProcessorCount;

    cudaFuncSetAttribute(k_steps, cudaFuncAttributeMaxDynamicSharedMemorySize, SMEM_T);

    k_init0<<<(Bc * Nc) / 1024, 256>>>(inp, state);
    k_steps<<<G, 512, SMEM_T>>>(state, W, beta, tau, G);
}

// round 16
// speedup vs baseline: 1.0177x; 1.0177x over previous
#include <cuda_runtime.h>
#include <cuda_fp16.h>
#include <cstdint>
#include <math.h>

// Problem dims (fixed by the dataset)
#define Bc 256
#define Nc 4096
#define Mc 16384
#define STEPS 50

// ---------------------------------------------------------------------------
// Device-global scratch
// ---------------------------------------------------------------------------
__device__ __half g_Wh[(size_t)Mc * Nc];    // W fp16 [m][n] (both GEMMs)
__device__ __half g_sh[(size_t)Bc * Nc];    // state fp16 [b][n]
__device__ __half g_fh[(size_t)Bc * Mc];    // e = exp(beta*h) fp16 [b][m]
__device__ float  g_fsumP[2][Bc];           // parity row sums
__device__ float  g_vpart[4][(size_t)Bc * Nc];
__device__ float  g_norm[STEPS];
__device__ unsigned g_cntP[2][4];           // parity per-slice g1 completion
__device__ unsigned g_tickP[2];             // parity g2 ticket counters
__device__ unsigned g_cntN[2][32];          // parity per-column g2 completion
__device__ unsigned g_tickU[2];             // parity update ticket counters

__device__ unsigned g_cnt_bar;
__device__ volatile unsigned g_gen_bar;

// ---------------------------------------------------------------------------
// PTX helpers (sm_80-era, legal on plain sm_103)
// ---------------------------------------------------------------------------
__device__ __forceinline__ uint32_t s2u(const void* p) {
    return (uint32_t)__cvta_generic_to_shared(p);
}
__device__ __forceinline__ void cpa16(uint32_t dst, const void* src) {
    asm volatile("cp.async.cg.shared.global [%0], [%1], 16;" :: "r"(dst), "l"(src));
}
#define CP_COMMIT() asm volatile("cp.async.commit_group;" ::: "memory")
#define CP_WAIT(n)  asm volatile("cp.async.wait_group %0;" :: "n"(n) : "memory")

__device__ __forceinline__ void ldm4(uint32_t* r, uint32_t addr) {
    asm volatile("ldmatrix.sync.aligned.m8n8.x4.shared.b16 {%0,%1,%2,%3}, [%4];"
                 : "=r"(r[0]), "=r"(r[1]), "=r"(r[2]), "=r"(r[3]) : "r"(addr));
}
__device__ __forceinline__ void ldm4t(uint32_t* r, uint32_t addr) {
    asm volatile("ldmatrix.sync.aligned.m8n8.x4.trans.shared.b16 {%0,%1,%2,%3}, [%4];"
                 : "=r"(r[0]), "=r"(r[1]), "=r"(r[2]), "=r"(r[3]) : "r"(addr));
}
__device__ __forceinline__ void mma16816(float* d, const uint32_t* a,
                                         uint32_t b0, uint32_t b1) {
    asm volatile(
        "mma.sync.aligned.m16n8k16.row.col.f32.f16.f16.f32 "
        "{%0,%1,%2,%3}, {%4,%5,%6,%7}, {%8,%9}, {%0,%1,%2,%3};"
        : "+f"(d[0]), "+f"(d[1]), "+f"(d[2]), "+f"(d[3])
        : "r"(a[0]), "r"(a[1]), "r"(a[2]), "r"(a[3]), "r"(b0), "r"(b1));
}

// ---------------------------------------------------------------------------
// Software global barrier (grid == #SMs, 1 CTA/SM -> co-resident)
// ---------------------------------------------------------------------------
__device__ __forceinline__ void gbar(int G) {
    __syncthreads();
    if (threadIdx.x == 0) {
        __threadfence();
        unsigned my = g_gen_bar;
        unsigned old = atomicAdd(&g_cnt_bar, 1u);
        if (old == (unsigned)G - 1u) {
            g_cnt_bar = 0u;
            __threadfence();
            g_gen_bar = my + 1u;
        } else {
            while (g_gen_bar == my) __nanosleep(64);
        }
        __threadfence();
    }
    __syncthreads();
}

// ---------------------------------------------------------------------------
// Prologue: W -> fp16, state <- input (+fp16), zero all step state
// ---------------------------------------------------------------------------
__global__ void __launch_bounds__(256) k_prep(const float* __restrict__ W,
                                              const float* __restrict__ inp,
                                              float* __restrict__ state) {
    size_t i = (size_t)blockIdx.x * 1024 + threadIdx.x * 4;
    float4 v = *(const float4*)(W + i);
    *(__half2*)(g_Wh + i)     = __floats2half2_rn(v.x, v.y);
    *(__half2*)(g_Wh + i + 2) = __floats2half2_rn(v.z, v.w);

    if (blockIdx.x < (Bc * Nc) / 1024) {
        float4 s = *(const float4*)(inp + i);
        *(float4*)(state + i) = s;
        *(__half2*)(g_sh + i)     = __floats2half2_rn(s.x, s.y);
        *(__half2*)(g_sh + i + 2) = __floats2half2_rn(s.z, s.w);
    }
    int gid = blockIdx.x * 256 + threadIdx.x;
    if (gid < STEPS) g_norm[gid] = 0.0f;
    if (gid < Bc) { g_fsumP[0][gid] = 0.0f; g_fsumP[1][gid] = 0.0f; }
    if (gid < 4)  { g_cntP[0][gid] = 0u;    g_cntP[1][gid] = 0u; }
    if (gid < 32) { g_cntN[0][gid] = 0u;    g_cntN[1][gid] = 0u; }
    if (gid == 40) { g_tickP[0] = 0u; g_tickP[1] = 0u; }
    if (gid == 41) { g_tickU[0] = 0u; g_tickU[1] = 0u; }
}

// ---------------------------------------------------------------------------
// Shared sizes (R13-proven)
// ---------------------------------------------------------------------------
#define KCH    64
#define ROWB   144                   // K-major row stride (128B + 16B pad)
#define A1_T   (256 * ROWB)          // 36864 B (A tile, 256 rows)
#define STG1   (A1_T + 128 * ROWB)   // 55296 B (GEMM1 stage)
#define STG2   (A1_T + 64 * 256)     // 53248 B (GEMM2 stage)
#define SMEM_T (2 * STG1)            // 110592 B

// ---------------------------------------------------------------------------
// GEMM1 tile: C[256(b) x 128(m)] = state[b][k] * W[m][k], K=4096, 128 tiles.
// 16 warps 4(b) x 4(m), warp tile 64x32. 2-stage cp.async, 1 sync/chunk.
// Epilogue: e = __expf(beta*acc) -> g_fh + row sums; then slice-signal.
// ---------------------------------------------------------------------------
__device__ __forceinline__ void load_g1(uint32_t sbase, int tid,
                                        const __half* Bp, int ch) {
#pragma unroll
    for (int t2 = 0; t2 < 4; t2++) {           // A: 256 rows x 8 segs
        int idx = tid + t2 * 512;
        int r = idx >> 3, q = idx & 7;
        cpa16(sbase + (uint32_t)(r * ROWB + q * 16),
              g_sh + (size_t)r * Nc + ch * KCH + q * 8);
    }
#pragma unroll
    for (int t2 = 0; t2 < 2; t2++) {           // B: 128 rows x 8 segs
        int idx = tid + t2 * 512;
        int r = idx >> 3, q = idx & 7;
        cpa16(sbase + A1_T + (uint32_t)(r * ROWB + q * 16),
              Bp + (size_t)r * Nc + ch * KCH + q * 8);
    }
}

__device__ void g1_tile(char* smem, int t, float beta,
                        float* fsumA, unsigned* cntA) {
    const int tid = threadIdx.x;
    const int wid = tid >> 5;
    const int lid = tid & 31;
    const int rw  = wid & 3;
    const int cw  = wid >> 2;
    const uint32_t sb = s2u(smem);

    const int c0 = t * 128;
    const __half* Bp = g_Wh + (size_t)c0 * Nc;

    float acc[4][4][4];
#pragma unroll
    for (int i = 0; i < 4; i++)
#pragma unroll
        for (int j = 0; j < 4; j++)
#pragma unroll
            for (int v = 0; v < 4; v++) acc[i][j][v] = 0.0f;

    const int lrow = ((lid >> 3) & 1) * 8 + (lid & 7);
    const int lkb  = (lid >> 4) * 16;

    load_g1(sb, tid, Bp, 0);
    CP_COMMIT();

    for (int ch = 0; ch < 64; ++ch) {
        const uint32_t cur = sb + (uint32_t)(ch & 1) * STG1;
        CP_WAIT(0);
        __syncthreads();
        if (ch + 1 < 64) {
            load_g1(sb + (uint32_t)((ch + 1) & 1) * STG1, tid, Bp, ch + 1);
            CP_COMMIT();
        }

#pragma unroll
        for (int ks = 0; ks < 4; ++ks) {
            uint32_t aF[4][4];
            uint32_t bF[2][4];
#pragma unroll
            for (int sub = 0; sub < 4; ++sub) {
                uint32_t ra = (uint32_t)((rw * 64 + sub * 16 + lrow) * ROWB
                                         + ks * 32 + lkb);
                ldm4(aF[sub], cur + ra);
            }
#pragma unroll
            for (int cg = 0; cg < 2; ++cg) {
                uint32_t rb = (uint32_t)((cw * 32 + cg * 16 + lrow) * ROWB
                                         + ks * 32 + lkb);
                ldm4(bF[cg], cur + A1_T + rb);
            }
#pragma unroll
            for (int sub = 0; sub < 4; ++sub)
#pragma unroll
                for (int cg = 0; cg < 2; ++cg)
#pragma unroll
                    for (int hf = 0; hf < 2; ++hf)
                        mma16816(acc[sub][cg * 2 + hf], aF[sub],
                                 bF[cg][hf], bF[cg][hf + 2]);
        }
    }
    __syncthreads();   // stages dead; smem reusable

    // Epilogue: e = __expf(beta*h) -> fp16 g_fh; row sums -> fsumA
    const int gr = lid >> 2;
    const int gc = (lid & 3) * 2;
    float* rsum = (float*)smem;
    if (tid < 256) rsum[tid] = 0.0f;
    __syncthreads();

#pragma unroll
    for (int sub = 0; sub < 4; ++sub) {
        const int rbase = rw * 64 + sub * 16 + gr;
        float s0 = 0.0f, s1 = 0.0f;
#pragma unroll
        for (int nt = 0; nt < 4; ++nt) {
            float e0 = __expf(beta * acc[sub][nt][0]);
            float e1 = __expf(beta * acc[sub][nt][1]);
            float e2 = __expf(beta * acc[sub][nt][2]);
            float e3 = __expf(beta * acc[sub][nt][3]);
            const int col = c0 + cw * 32 + nt * 8 + gc;
            *(__half2*)(g_fh + (size_t)rbase * Mc + col) =
                __floats2half2_rn(e0, e1);
            *(__half2*)(g_fh + (size_t)(rbase + 8) * Mc + col) =
                __floats2half2_rn(e2, e3);
            s0 += e0 + e1;
            s1 += e2 + e3;
        }
        s0 += __shfl_xor_sync(0xFFFFFFFF, s0, 1);
        s0 += __shfl_xor_sync(0xFFFFFFFF, s0, 2);
        s1 += __shfl_xor_sync(0xFFFFFFFF, s1, 1);
        s1 += __shfl_xor_sync(0xFFFFFFFF, s1, 2);
        if ((lid & 3) == 0) {
            atomicAdd(&rsum[rbase], s0);
            atomicAdd(&rsum[rbase + 8], s1);
        }
    }
    __syncthreads();
    if (tid < 256) atomicAdd(&fsumA[tid], rsum[tid]);
    // release: g_fh stores + fsum atomics, then slice signal
    __threadfence();
    __syncthreads();
    if (tid == 0) atomicAdd(&cntA[t >> 5], 1u);
}

// ---------------------------------------------------------------------------
// GEMM2 tile: u[256(b) x 128(n)] = e[b][k] * W[k][n], z-split 4 (K=4096 each),
// 128 tiles, z = t>>5, col-block c = t&31. Signals cntN[c] on completion.
// ---------------------------------------------------------------------------
__device__ __forceinline__ void load_g2(uint32_t sbase, int tid,
                                        const __half* Ap, const __half* Bp, int ch) {
#pragma unroll
    for (int t2 = 0; t2 < 4; t2++) {           // A: 256 rows x 8 segs (K-major)
        int idx = tid + t2 * 512;
        int r = idx >> 3, q = idx & 7;
        cpa16(sbase + (uint32_t)(r * ROWB + q * 16),
              Ap + (size_t)r * Mc + ch * KCH + q * 8);
    }
#pragma unroll
    for (int t2 = 0; t2 < 2; t2++) {           // B: 64 k-rows x 16 segs, XOR sw
        int idx = tid + t2 * 512;
        int r = idx >> 4, q = idx & 15;
        cpa16(sbase + A1_T + (uint32_t)(r * 256 + ((q ^ (r & 7)) * 16)),
              Bp + (size_t)(ch * KCH + r) * Nc + q * 8);
    }
}

__device__ void g2_tile(char* smem, int t, unsigned* cntN) {
    const int tid = threadIdx.x;
    const int wid = tid >> 5;
    const int lid = tid & 31;
    const int rw  = wid & 3;
    const int cw  = wid >> 2;
    const uint32_t sb = s2u(smem);

    const int z  = t >> 5;
    const int c0 = (t & 31) * 128;
    const size_t koff = (size_t)z * 4096;

    const __half* Ap = g_fh + koff;
    const __half* Bp = g_Wh + koff * Nc + c0;
    float* out = &g_vpart[z][0];

    float acc[4][4][4];
#pragma unroll
    for (int i = 0; i < 4; i++)
#pragma unroll
        for (int j = 0; j < 4; j++)
#pragma unroll
            for (int v = 0; v < 4; v++) acc[i][j][v] = 0.0f;

    const int lrow = ((lid >> 3) & 1) * 8 + (lid & 7);
    const int lkb  = (lid >> 4) * 16;
    const int kr   = ((lid >> 4) & 1) * 8 + (lid & 7);
    const int nso  = (lid >> 3) & 1;

    load_g2(sb, tid, Ap, Bp, 0);
    CP_COMMIT();

    for (int ch = 0; ch < 64; ++ch) {
        const uint32_t cur = sb + (uint32_t)(ch & 1) * STG2;
        CP_WAIT(0);
        __syncthreads();
        if (ch + 1 < 64) {
            load_g2(sb + (uint32_t)((ch + 1) & 1) * STG2, tid, Ap, Bp, ch + 1);
            CP_COMMIT();
        }

#pragma unroll
        for (int ks = 0; ks < 4; ++ks) {
            uint32_t aF[4][4];
            uint32_t bF[2][4];
#pragma unroll
            for (int sub = 0; sub < 4; ++sub) {
                uint32_t ra = (uint32_t)((rw * 64 + sub * 16 + lrow) * ROWB
                                         + ks * 32 + lkb);
                ldm4(aF[sub], cur + ra);
            }
#pragma unroll
            for (int cg = 0; cg < 2; ++cg) {
                const int nseg = cw * 4 + cg * 2 + nso;
                uint32_t rb = (uint32_t)((ks * 16 + kr) * 256
                                         + ((nseg ^ (lid & 7)) * 16));
                ldm4t(bF[cg], cur + A1_T + rb);
            }
#pragma unroll
            for (int sub = 0; sub < 4; ++sub)
#pragma unroll
                for (int cg = 0; cg < 2; ++cg)
#pragma unroll
                    for (int hf = 0; hf < 2; ++hf)
                        mma16816(acc[sub][cg * 2 + hf], aF[sub],
                                 bF[cg][hf], bF[cg][hf + 2]);
        }
    }
    __syncthreads();

    const int gr = lid >> 2;
    const int gc = (lid & 3) * 2;
#pragma unroll
    for (int sub = 0; sub < 4; ++sub) {
        const int rbase = rw * 64 + sub * 16 + gr;
#pragma unroll
        for (int nt = 0; nt < 4; ++nt) {
            const int col = c0 + cw * 32 + nt * 8 + gc;
            *(float2*)(out + (size_t)rbase * Nc + col) =
                make_float2(acc[sub][nt][0], acc[sub][nt][1]);
            *(float2*)(out + (size_t)(rbase + 8) * Nc + col) =
                make_float2(acc[sub][nt][2], acc[sub][nt][3]);
        }
    }
    // release vpart stores, then column signal
    __threadfence();
    __syncthreads();
    if (tid == 0) atomicAdd(&cntN[t & 31], 1u);
}

// ---------------------------------------------------------------------------
// Update tile: column block u (128 n-cols, all 256 b-rows).
// v = (sum of 4 z-partials) / rowsum; state += (v - state)/tau; norm accum.
// All global reads via __ldcg (L2) — writers were other SMs.
// ---------------------------------------------------------------------------
__device__ __forceinline__ float upd_tile(int u, float* state,
                                          const float* fsumA, float invtau) {
    const int tid = threadIdx.x;
    const int col = u * 128 + (tid & 31) * 4;
    float sumsq = 0.0f;
    for (int b = tid >> 5; b < Bc; b += 16) {
        const size_t i = (size_t)b * Nc + col;
        float4 v0 = __ldcg((const float4*)&g_vpart[0][i]);
        float4 v1 = __ldcg((const float4*)&g_vpart[1][i]);
        float4 v2 = __ldcg((const float4*)&g_vpart[2][i]);
        float4 v3 = __ldcg((const float4*)&g_vpart[3][i]);
        float4 s  = __ldcg((const float4*)&state[i]);
        const float inv = 1.0f / __ldcg(&fsumA[b]);
        float vx = (v0.x + v1.x + v2.x + v3.x) * inv;
        float vy = (v0.y + v1.y + v2.y + v3.y) * inv;
        float vz = (v0.z + v1.z + v2.z + v3.z) * inv;
        float vw = (v0.w + v1.w + v2.w + v3.w) * inv;
        float n0 = s.x + invtau * (vx - s.x);
        float n1 = s.y + invtau * (vy - s.y);
        float n2 = s.z + invtau * (vz - s.z);
        float n3 = s.w + invtau * (vw - s.w);
        float d0 = n0 - s.x, d1 = n1 - s.y, d2 = n2 - s.z, d3 = n3 - s.w;
        sumsq += d0 * d0 + d1 * d1 + d2 * d2 + d3 * d3;
        *(float4*)&state[i] = make_float4(n0, n1, n2, n3);
        *(__half2*)(g_sh + i)     = __floats2half2_rn(n0, n1);
        *(__half2*)(g_sh + i + 2) = __floats2half2_rn(n2, n3);
    }
    return sumsq;
}

// ---------------------------------------------------------------------------
// Persistent kernel: all steps; g1->g2->update fully dataflow-overlapped;
// ONE global barrier per step.
// ---------------------------------------------------------------------------
__global__ void __launch_bounds__(512, 1) k_steps(float* __restrict__ state,
                                                  const float* __restrict__ beta_p,
                                                  const float* __restrict__ tau_p,
                                                  int G) {
    extern __shared__ char smem[];
    float* red = (float*)smem;
    const int tid = threadIdx.x;
    const float beta = *beta_p;
    const float invtau = 1.0f / (*tau_p);

    for (int step = 0; step < STEPS; ++step) {
        const int p = step & 1;
        float*    fsumA = g_fsumP[p];
        unsigned* cntA  = g_cntP[p];
        unsigned* cntN  = g_cntN[p];

        // GEMM1 + fused exp/rowsum (128 tiles); slice-signals g2
        for (int t = blockIdx.x; t < 128; t += G)
            g1_tile(smem, t, beta, fsumA, cntA);

        // CTA 0 zeros next-parity control state (safe: last readers finished
        // before the previous step's gbar; next writers start after this
        // step's gbar)
        if (blockIdx.x == 0) {
            if (tid < Bc) g_fsumP[p ^ 1][tid] = 0.0f;
            if (tid < 4)  g_cntP[p ^ 1][tid] = 0u;
            if (tid < 32) g_cntN[p ^ 1][tid] = 0u;
            if (tid == 40) g_tickP[p ^ 1] = 0u;
            if (tid == 41) g_tickU[p ^ 1] = 0u;
        }

        // GEMM2 (128 tiles, ticket-dispatched, waits only on its k-slice)
        for (;;) {
            int* ts = (int*)smem;
            if (tid == 0) ts[0] = (int)atomicAdd(&g_tickP[p], 1u);
            __syncthreads();
            const int t = ts[0];
            __syncthreads();
            if (t >= 128) break;
            if (tid == 0) {
                while (*((volatile unsigned*)&cntA[t >> 5]) < 32u)
                    __nanosleep(32);
            }
            __syncthreads();
            g2_tile(smem, t, cntN);
        }

        // Update (32 column tiles, ticket-dispatched, waits on its column)
        float sumsq = 0.0f;
        for (;;) {
            int* ts = (int*)smem;
            if (tid == 0) ts[0] = (int)atomicAdd(&g_tickU[p], 1u);
            __syncthreads();
            const int u = ts[0];
            __syncthreads();
            if (u >= 32) break;
            if (tid == 0) {
                while (*((volatile unsigned*)&cntN[u]) < 4u)
                    __nanosleep(32);
            }
            __syncthreads();
            sumsq += upd_tile(u, state, fsumA, invtau);
        }
        __syncthreads();
        red[tid] = sumsq;
        __syncthreads();
        for (int s = 256; s > 0; s >>= 1) {
            if (tid < s) red[tid] += red[tid + s];
            __syncthreads();
        }
        if (tid == 0 && red[0] != 0.0f) atomicAdd(&g_norm[step], red[0]);
        gbar(G);

        float nrm = *(volatile float*)&g_norm[step];
        if (sqrtf(nrm) <= 1e-3f) break;
        __syncthreads();
    }
}

// ---------------------------------------------------------------------------
// kernel_launch
// ---------------------------------------------------------------------------
extern "C" void kernel_launch(void* const* d_in, const int* in_sizes, int n_in,
                              void* d_out, int out_size) {
    const float* inp  = (const float*)d_in[0];
    const float* W    = (const float*)d_in[1];
    const float* beta = (const float*)d_in[2];
    const float* tau  = (const float*)d_in[3];
    float* state = (float*)d_out;

    int dev = 0;
    cudaGetDevice(&dev);
    cudaDeviceProp props;
    cudaGetDeviceProperties(&props, dev);
    const int G = props.multiProcessorCount;

    cudaFuncSetAttribute(k_steps, cudaFuncAttributeMaxDynamicSharedMemorySize, SMEM_T);

    k_prep<<<(size_t)Mc * Nc / 1024, 256>>>(W, inp, state);
    k_steps<<<G, 512, SMEM_T>>>(state, beta, tau, G);
}